// round 9
// baseline (speedup 1.0000x reference)
#include <cuda_runtime.h>
#include <cuda_bf16.h>
#include <cstdint>

// Shifted-window attention via warp-level bf16 mma.sync (m16n8k16), hi/lo
// 3-product split. One CTA (64 thr, 2 warps) per window; warp owns 32 rows
// (2 m-tiles) => K/V LDSM traffic halved vs 16-row warps, B-frag reuse x2.
// Q direct global->regs; P kept in registers. Smem: K,V hi/lo + bias.

#define TPB 64
#define NBLK 4096

#define SM_KH 0
#define SM_KL 8192
#define SM_VH 16384
#define SM_VL 24576
#define SM_BIAS 32768    // 127 floats
#define SM_TOTAL 33408

#define SWZ(x) ((x) ^ (((x) >> 3) & 0x70))

__device__ __forceinline__ uint32_t smem_u32(const void* p){
    uint32_t a;
    asm("{ .reg .u64 t; cvta.to.shared.u64 t, %1; cvt.u32.u64 %0, t; }" : "=r"(a) : "l"(p));
    return a;
}
// pack floats a(lo half),b(hi half) to bf16x2 hi-part and residual lo-part
__device__ __forceinline__ void split2(float a, float b, uint32_t& hi, uint32_t& lo){
    uint32_t h;
    asm("cvt.rn.bf16x2.f32 %0, %1, %2;" : "=r"(h) : "f"(b), "f"(a));
    float ha = __uint_as_float(h << 16);
    float hb = __uint_as_float(h & 0xffff0000u);
    uint32_t l;
    asm("cvt.rn.bf16x2.f32 %0, %1, %2;" : "=r"(l) : "f"(b - hb), "f"(a - ha));
    hi = h; lo = l;
}
#define LDSM_X4(r0,r1,r2,r3, a) \
    asm volatile("ldmatrix.sync.aligned.m8n8.x4.shared.b16 {%0,%1,%2,%3}, [%4];" \
        : "=r"(r0),"=r"(r1),"=r"(r2),"=r"(r3) : "r"(a))
#define LDSM_X4_T(r0,r1,r2,r3, a) \
    asm volatile("ldmatrix.sync.aligned.m8n8.x4.trans.shared.b16 {%0,%1,%2,%3}, [%4];" \
        : "=r"(r0),"=r"(r1),"=r"(r2),"=r"(r3) : "r"(a))
#define MMA(d, a0,a1,a2,a3, b0,b1) \
    asm volatile("mma.sync.aligned.m16n8k16.row.col.f32.bf16.bf16.f32 " \
        "{%0,%1,%2,%3}, {%4,%5,%6,%7}, {%8,%9}, {%0,%1,%2,%3};" \
        : "+f"((d)[0]),"+f"((d)[1]),"+f"((d)[2]),"+f"((d)[3]) \
        : "r"(a0),"r"(a1),"r"(a2),"r"(a3), "r"(b0),"r"(b1))

extern "C" __global__ void __launch_bounds__(TPB, 6)
win_attn_mma(const float* __restrict__ q, const float* __restrict__ k,
             const float* __restrict__ v, const float* __restrict__ tab,
             float* __restrict__ out)
{
    extern __shared__ __align__(128) char smem[];
    const uint32_t sb = smem_u32(smem);
    const int tid = threadIdx.x;
    const int g   = blockIdx.x;
    const int bb  = g >> 7;          // batch
    const int w   = g & 127;         // window
    const int start = w * 64 + 32;   // cyclic shift by -32 as gather
    const long batch_base = (long)bb * 8192;

    // ---- load K,V window: fp32 -> bf16 hi/lo, swizzled 128B rows ----
    #pragma unroll
    for (int it = 0; it < 16; ++it) {
        int idx = it * TPB + tid;        // 0..1023
        int p = idx >> 4, c4 = idx & 15; // row p, cols 4c4..4c4+3
        int row = (start + p) & 8191;
        long go = (batch_base + row) * 64 + c4 * 4;
        uint32_t so = SWZ((uint32_t)(p * 128 + c4 * 8));
        float4 kv = *(const float4*)(k + go);
        float4 vv = *(const float4*)(v + go);
        uint32_t h0,l0,h1,l1;
        split2(kv.x, kv.y, h0, l0); split2(kv.z, kv.w, h1, l1);
        *(uint2*)(smem + SM_KH + so) = make_uint2(h0, h1);
        *(uint2*)(smem + SM_KL + so) = make_uint2(l0, l1);
        split2(vv.x, vv.y, h0, l0); split2(vv.z, vv.w, h1, l1);
        *(uint2*)(smem + SM_VH + so) = make_uint2(h0, h1);
        *(uint2*)(smem + SM_VL + so) = make_uint2(l0, l1);
    }
    for (int i = tid; i < 127; i += TPB) ((float*)(smem + SM_BIAS))[i] = tab[i];

    const int wid  = tid >> 5, lane = tid & 31;
    const int gq   = lane >> 2, t = lane & 3;
    const int R0   = wid * 32;       // warp owns rows R0..R0+31 (2 m-tiles)

    // ---- Q A-fragments: direct global loads (warp-private rows) ----
    uint32_t qah[2][16], qal[2][16];   // [mt][kc*4 + {a0,a1,a2,a3}]
    #pragma unroll
    for (int mt = 0; mt < 2; ++mt) {
        int rl = R0 + mt * 16 + gq;
        const float* qlo = q + (batch_base + ((start + rl) & 8191)) * 64 + 2 * t;
        const float* qhi = q + (batch_base + ((start + rl + 8) & 8191)) * 64 + 2 * t;
        #pragma unroll
        for (int kc = 0; kc < 4; ++kc) {
            float2 f0 = *(const float2*)(qlo + kc * 16);
            float2 f1 = *(const float2*)(qhi + kc * 16);
            float2 f2 = *(const float2*)(qlo + kc * 16 + 8);
            float2 f3 = *(const float2*)(qhi + kc * 16 + 8);
            split2(f0.x, f0.y, qah[mt][kc*4+0], qal[mt][kc*4+0]);
            split2(f1.x, f1.y, qah[mt][kc*4+1], qal[mt][kc*4+1]);
            split2(f2.x, f2.y, qah[mt][kc*4+2], qal[mt][kc*4+2]);
            split2(f3.x, f3.y, qah[mt][kc*4+3], qal[mt][kc*4+3]);
        }
    }
    __syncthreads();

    float acc[2][8][4];
    #pragma unroll
    for (int mt = 0; mt < 2; ++mt)
        #pragma unroll
        for (int nt = 0; nt < 8; ++nt)
            #pragma unroll
            for (int e = 0; e < 4; ++e) acc[mt][nt][e] = 0.0f;

    // ---- gemm1: S = Q K^T (hh + hl + lh); each B-frag feeds both m-tiles ----
    #pragma unroll
    for (int kc = 0; kc < 4; ++kc) {
        uint32_t grp = (uint32_t)(lane >> 3), l8 = (uint32_t)(lane & 7);
        uint32_t nrow_b = ((grp >> 1) << 3) + l8;
        uint32_t kcol_b = (uint32_t)kc * 32 + ((grp & 1) << 4);
        #pragma unroll
        for (int ntp = 0; ntp < 4; ++ntp) {
            uint32_t boff = SWZ((nrow_b + ntp * 16) * 128 + kcol_b);
            uint32_t bh0,bh1,bh2,bh3, bl0,bl1,bl2,bl3;
            LDSM_X4(bh0,bh1,bh2,bh3, sb + SM_KH + boff);
            LDSM_X4(bl0,bl1,bl2,bl3, sb + SM_KL + boff);
            #pragma unroll
            for (int mt = 0; mt < 2; ++mt) {
                uint32_t ah0 = qah[mt][kc*4+0], ah1 = qah[mt][kc*4+1];
                uint32_t ah2 = qah[mt][kc*4+2], ah3 = qah[mt][kc*4+3];
                uint32_t al0 = qal[mt][kc*4+0], al1 = qal[mt][kc*4+1];
                uint32_t al2 = qal[mt][kc*4+2], al3 = qal[mt][kc*4+3];
                MMA(acc[mt][2*ntp],   ah0,ah1,ah2,ah3, bh0,bh1);
                MMA(acc[mt][2*ntp],   ah0,ah1,ah2,ah3, bl0,bl1);
                MMA(acc[mt][2*ntp],   al0,al1,al2,al3, bh0,bh1);
                MMA(acc[mt][2*ntp+1], ah0,ah1,ah2,ah3, bh2,bh3);
                MMA(acc[mt][2*ntp+1], ah0,ah1,ah2,ah3, bl2,bl3);
                MMA(acc[mt][2*ntp+1], al0,al1,al2,al3, bh2,bh3);
            }
        }
    }

    // ---- epilogue: scale + bias + mask, softmax over each row ----
    {
        const float* bt = (const float*)(smem + SM_BIAS);
        const bool dm = (w == 127);
        #pragma unroll
        for (int mt = 0; mt < 2; ++mt) {
            int r_lo = R0 + mt * 16 + gq, r_hi = r_lo + 8;
            float mlo = -1e30f, mhi = -1e30f;
            #pragma unroll
            for (int nt = 0; nt < 8; ++nt) {
                int c0 = nt * 8 + 2 * t;
                float b0v = bt[r_lo - c0 + 63], b1v = bt[r_lo - c0 + 62];
                float b2v = bt[r_hi - c0 + 63], b3v = bt[r_hi - c0 + 62];
                float mk_lo = (dm && ((r_lo < 32) != (c0 < 32))) ? -100.0f : 0.0f;
                float mk_hi = (dm && ((r_hi < 32) != (c0 < 32))) ? -100.0f : 0.0f;
                acc[mt][nt][0] = acc[mt][nt][0] * 0.125f + b0v + mk_lo;
                acc[mt][nt][1] = acc[mt][nt][1] * 0.125f + b1v + mk_lo;
                acc[mt][nt][2] = acc[mt][nt][2] * 0.125f + b2v + mk_hi;
                acc[mt][nt][3] = acc[mt][nt][3] * 0.125f + b3v + mk_hi;
                mlo = fmaxf(mlo, fmaxf(acc[mt][nt][0], acc[mt][nt][1]));
                mhi = fmaxf(mhi, fmaxf(acc[mt][nt][2], acc[mt][nt][3]));
            }
            mlo = fmaxf(mlo, __shfl_xor_sync(0xffffffffu, mlo, 1));
            mlo = fmaxf(mlo, __shfl_xor_sync(0xffffffffu, mlo, 2));
            mhi = fmaxf(mhi, __shfl_xor_sync(0xffffffffu, mhi, 1));
            mhi = fmaxf(mhi, __shfl_xor_sync(0xffffffffu, mhi, 2));
            float slo = 0.0f, shi = 0.0f;
            #pragma unroll
            for (int nt = 0; nt < 8; ++nt) {
                acc[mt][nt][0] = __expf(acc[mt][nt][0] - mlo);
                acc[mt][nt][1] = __expf(acc[mt][nt][1] - mlo);
                acc[mt][nt][2] = __expf(acc[mt][nt][2] - mhi);
                acc[mt][nt][3] = __expf(acc[mt][nt][3] - mhi);
                slo += acc[mt][nt][0] + acc[mt][nt][1];
                shi += acc[mt][nt][2] + acc[mt][nt][3];
            }
            slo += __shfl_xor_sync(0xffffffffu, slo, 1);
            slo += __shfl_xor_sync(0xffffffffu, slo, 2);
            shi += __shfl_xor_sync(0xffffffffu, shi, 1);
            shi += __shfl_xor_sync(0xffffffffu, shi, 2);
            float ilo = __fdividef(1.0f, slo), ihi = __fdividef(1.0f, shi);
            #pragma unroll
            for (int nt = 0; nt < 8; ++nt) {
                acc[mt][nt][0] *= ilo; acc[mt][nt][1] *= ilo;
                acc[mt][nt][2] *= ihi; acc[mt][nt][3] *= ihi;
            }
        }
    }

    // ---- write attn ----
    {
        float* oat = out + 16777216L + (long)g * 4096;
        #pragma unroll
        for (int mt = 0; mt < 2; ++mt) {
            int r_lo = R0 + mt * 16 + gq, r_hi = r_lo + 8;
            #pragma unroll
            for (int nt = 0; nt < 8; ++nt) {
                int c0 = nt * 8 + 2 * t;
                *(float2*)(oat + r_lo * 64 + c0) = make_float2(acc[mt][nt][0], acc[mt][nt][1]);
                *(float2*)(oat + r_hi * 64 + c0) = make_float2(acc[mt][nt][2], acc[mt][nt][3]);
            }
        }
    }

    // ---- convert P (in acc) directly into gemm2 A-fragments ----
    uint32_t pah[2][16], pal[2][16];
    #pragma unroll
    for (int mt = 0; mt < 2; ++mt)
        #pragma unroll
        for (int kc = 0; kc < 4; ++kc) {
            split2(acc[mt][2*kc][0],   acc[mt][2*kc][1],   pah[mt][kc*4+0], pal[mt][kc*4+0]);
            split2(acc[mt][2*kc][2],   acc[mt][2*kc][3],   pah[mt][kc*4+1], pal[mt][kc*4+1]);
            split2(acc[mt][2*kc+1][0], acc[mt][2*kc+1][1], pah[mt][kc*4+2], pal[mt][kc*4+2]);
            split2(acc[mt][2*kc+1][2], acc[mt][2*kc+1][3], pah[mt][kc*4+3], pal[mt][kc*4+3]);
        }

    // ---- gemm2: O = P V (hh + hl + lh), V via ldmatrix.trans ----
    #pragma unroll
    for (int mt = 0; mt < 2; ++mt)
        #pragma unroll
        for (int nt = 0; nt < 8; ++nt)
            #pragma unroll
            for (int e = 0; e < 4; ++e) acc[mt][nt][e] = 0.0f;

    #pragma unroll
    for (int kc = 0; kc < 4; ++kc) {
        uint32_t grp = (uint32_t)(lane >> 3), l8 = (uint32_t)(lane & 7);
        uint32_t krow = (uint32_t)kc * 16 + ((grp & 1) << 3) + l8;
        uint32_t nbase = ((grp >> 1) << 3);
        #pragma unroll
        for (int ntp = 0; ntp < 4; ++ntp) {
            uint32_t boff = SWZ(krow * 128 + (nbase + ntp * 16) * 2);
            uint32_t bh0,bh1,bh2,bh3, bl0,bl1,bl2,bl3;
            LDSM_X4_T(bh0,bh1,bh2,bh3, sb + SM_VH + boff);
            LDSM_X4_T(bl0,bl1,bl2,bl3, sb + SM_VL + boff);
            #pragma unroll
            for (int mt = 0; mt < 2; ++mt) {
                uint32_t ah0 = pah[mt][kc*4+0], ah1 = pah[mt][kc*4+1];
                uint32_t ah2 = pah[mt][kc*4+2], ah3 = pah[mt][kc*4+3];
                uint32_t al0 = pal[mt][kc*4+0], al1 = pal[mt][kc*4+1];
                uint32_t al2 = pal[mt][kc*4+2], al3 = pal[mt][kc*4+3];
                MMA(acc[mt][2*ntp],   ah0,ah1,ah2,ah3, bh0,bh1);
                MMA(acc[mt][2*ntp],   ah0,ah1,ah2,ah3, bl0,bl1);
                MMA(acc[mt][2*ntp],   al0,al1,al2,al3, bh0,bh1);
                MMA(acc[mt][2*ntp+1], ah0,ah1,ah2,ah3, bh2,bh3);
                MMA(acc[mt][2*ntp+1], ah0,ah1,ah2,ah3, bl2,bl3);
                MMA(acc[mt][2*ntp+1], al0,al1,al2,al3, bh2,bh3);
            }
        }
    }

    // ---- write x with inverse cyclic shift ----
    #pragma unroll
    for (int mt = 0; mt < 2; ++mt) {
        int r_lo = R0 + mt * 16 + gq, r_hi = r_lo + 8;
        float* op_lo = out + (batch_base + ((start + r_lo) & 8191)) * 64;
        float* op_hi = out + (batch_base + ((start + r_hi) & 8191)) * 64;
        #pragma unroll
        for (int nt = 0; nt < 8; ++nt) {
            int c0 = nt * 8 + 2 * t;
            *(float2*)(op_lo + c0) = make_float2(acc[mt][nt][0], acc[mt][nt][1]);
            *(float2*)(op_hi + c0) = make_float2(acc[mt][nt][2], acc[mt][nt][3]);
        }
    }
}

extern "C" void kernel_launch(void* const* d_in, const int* in_sizes, int n_in,
                              void* d_out, int out_size)
{
    const float* q   = (const float*)d_in[0];
    const float* k   = (const float*)d_in[1];
    const float* v   = (const float*)d_in[2];
    const float* tab = (const float*)d_in[3];
    float* out = (float*)d_out;
    (void)in_sizes; (void)n_in; (void)out_size;

    cudaFuncSetAttribute(win_attn_mma,
                         cudaFuncAttributeMaxDynamicSharedMemorySize, SM_TOTAL);
    win_attn_mma<<<NBLK, TPB, SM_TOTAL>>>(q, k, v, tab, out);
}

// round 10
// speedup vs baseline: 1.0949x; 1.0949x over previous
#include <cuda_runtime.h>
#include <cuda_bf16.h>
#include <cstdint>

// Shifted-window attention via warp-level bf16 mma.sync (m16n8k16), hi/lo
// 3-product split. One CTA (128 thr) per window; warp owns 16 rows.
// Q direct global->regs (warp-private A-frags); P kept in registers
// (acc layout == A-frag layout). Smem only for K and V hi/lo tiles.

#define TPB 128
#define NBLK 4096

#define SM_KH 0
#define SM_KL 8192
#define SM_VH 16384
#define SM_VL 24576
#define SM_BIAS 32768    // 127 floats
#define SM_TOTAL 33408

#define SWZ(x) ((x) ^ (((x) >> 3) & 0x70))

__device__ __forceinline__ uint32_t smem_u32(const void* p){
    uint32_t a;
    asm("{ .reg .u64 t; cvta.to.shared.u64 t, %1; cvt.u32.u64 %0, t; }" : "=r"(a) : "l"(p));
    return a;
}
// pack floats a(lo half),b(hi half) to bf16x2 hi-part and residual lo-part
__device__ __forceinline__ void split2(float a, float b, uint32_t& hi, uint32_t& lo){
    uint32_t h;
    asm("cvt.rn.bf16x2.f32 %0, %1, %2;" : "=r"(h) : "f"(b), "f"(a));
    float ha = __uint_as_float(h << 16);
    float hb = __uint_as_float(h & 0xffff0000u);
    uint32_t l;
    asm("cvt.rn.bf16x2.f32 %0, %1, %2;" : "=r"(l) : "f"(b - hb), "f"(a - ha));
    hi = h; lo = l;
}
#define LDSM_X4(r0,r1,r2,r3, a) \
    asm volatile("ldmatrix.sync.aligned.m8n8.x4.shared.b16 {%0,%1,%2,%3}, [%4];" \
        : "=r"(r0),"=r"(r1),"=r"(r2),"=r"(r3) : "r"(a))
#define LDSM_X4_T(r0,r1,r2,r3, a) \
    asm volatile("ldmatrix.sync.aligned.m8n8.x4.trans.shared.b16 {%0,%1,%2,%3}, [%4];" \
        : "=r"(r0),"=r"(r1),"=r"(r2),"=r"(r3) : "r"(a))
#define MMA(d, a0,a1,a2,a3, b0,b1) \
    asm volatile("mma.sync.aligned.m16n8k16.row.col.f32.bf16.bf16.f32 " \
        "{%0,%1,%2,%3}, {%4,%5,%6,%7}, {%8,%9}, {%0,%1,%2,%3};" \
        : "+f"((d)[0]),"+f"((d)[1]),"+f"((d)[2]),"+f"((d)[3]) \
        : "r"(a0),"r"(a1),"r"(a2),"r"(a3), "r"(b0),"r"(b1))

extern "C" __global__ void __launch_bounds__(TPB, 6)
win_attn_mma(const float* __restrict__ q, const float* __restrict__ k,
             const float* __restrict__ v, const float* __restrict__ tab,
             float* __restrict__ out)
{
    extern __shared__ __align__(128) char smem[];
    const uint32_t sb = smem_u32(smem);
    const int tid = threadIdx.x;
    const int g   = blockIdx.x;
    const int bb  = g >> 7;          // batch
    const int w   = g & 127;         // window
    const int start = w * 64 + 32;   // cyclic shift by -32 as gather
    const long batch_base = (long)bb * 8192;

    // ---- load K,V window: fp32 -> bf16 hi/lo, 16B swizzled stores ----
    // thread handles 8 consecutive cols of one row per iter
    #pragma unroll
    for (int it = 0; it < 4; ++it) {
        int idx = it * TPB + tid;        // 0..511
        int p = idx >> 3, c8 = idx & 7;  // row p, cols 8c8..8c8+7
        int row = (start + p) & 8191;
        long go = (batch_base + row) * 64 + c8 * 8;
        uint32_t so = SWZ((uint32_t)(p * 128 + c8 * 16));
        float4 ka = *(const float4*)(k + go);
        float4 kb = *(const float4*)(k + go + 4);
        float4 va = *(const float4*)(v + go);
        float4 vb = *(const float4*)(v + go + 4);
        uint32_t h0,l0,h1,l1,h2,l2,h3,l3;
        split2(ka.x, ka.y, h0, l0); split2(ka.z, ka.w, h1, l1);
        split2(kb.x, kb.y, h2, l2); split2(kb.z, kb.w, h3, l3);
        *(uint4*)(smem + SM_KH + so) = make_uint4(h0, h1, h2, h3);
        *(uint4*)(smem + SM_KL + so) = make_uint4(l0, l1, l2, l3);
        split2(va.x, va.y, h0, l0); split2(va.z, va.w, h1, l1);
        split2(vb.x, vb.y, h2, l2); split2(vb.z, vb.w, h3, l3);
        *(uint4*)(smem + SM_VH + so) = make_uint4(h0, h1, h2, h3);
        *(uint4*)(smem + SM_VL + so) = make_uint4(l0, l1, l2, l3);
    }
    if (tid < 127) ((float*)(smem + SM_BIAS))[tid] = tab[tid];

    const int wid  = tid >> 5, lane = tid & 31;
    const int gq   = lane >> 2, t = lane & 3;
    const int R0   = wid * 16;
    const int r_lo = R0 + gq, r_hi = r_lo + 8;

    // ---- Q A-fragments: direct global loads (warp-private rows) ----
    const float* qlo = q + (batch_base + ((start + r_lo) & 8191)) * 64 + 2 * t;
    const float* qhi = q + (batch_base + ((start + r_hi) & 8191)) * 64 + 2 * t;
    uint32_t qah[16], qal[16];   // [kc*4 + {a0,a1,a2,a3}]
    #pragma unroll
    for (int kc = 0; kc < 4; ++kc) {
        float2 f0 = *(const float2*)(qlo + kc * 16);
        float2 f1 = *(const float2*)(qhi + kc * 16);
        float2 f2 = *(const float2*)(qlo + kc * 16 + 8);
        float2 f3 = *(const float2*)(qhi + kc * 16 + 8);
        split2(f0.x, f0.y, qah[kc*4+0], qal[kc*4+0]);
        split2(f1.x, f1.y, qah[kc*4+1], qal[kc*4+1]);
        split2(f2.x, f2.y, qah[kc*4+2], qal[kc*4+2]);
        split2(f3.x, f3.y, qah[kc*4+3], qal[kc*4+3]);
    }
    __syncthreads();

    float acc[8][4];
    #pragma unroll
    for (int nt = 0; nt < 8; ++nt)
        #pragma unroll
        for (int e = 0; e < 4; ++e) acc[nt][e] = 0.0f;

    // ---- gemm1: S = Q K^T (hh + hl + lh) ----
    #pragma unroll
    for (int kc = 0; kc < 4; ++kc) {
        uint32_t ah0 = qah[kc*4+0], ah1 = qah[kc*4+1], ah2 = qah[kc*4+2], ah3 = qah[kc*4+3];
        uint32_t al0 = qal[kc*4+0], al1 = qal[kc*4+1], al2 = qal[kc*4+2], al3 = qal[kc*4+3];
        uint32_t grp = (uint32_t)(lane >> 3), l8 = (uint32_t)(lane & 7);
        uint32_t nrow_b = ((grp >> 1) << 3) + l8;
        uint32_t kcol_b = (uint32_t)kc * 32 + ((grp & 1) << 4);
        #pragma unroll
        for (int ntp = 0; ntp < 4; ++ntp) {
            uint32_t boff = SWZ((nrow_b + ntp * 16) * 128 + kcol_b);
            uint32_t bh0,bh1,bh2,bh3, bl0,bl1,bl2,bl3;
            LDSM_X4(bh0,bh1,bh2,bh3, sb + SM_KH + boff);
            LDSM_X4(bl0,bl1,bl2,bl3, sb + SM_KL + boff);
            MMA(acc[2*ntp],   ah0,ah1,ah2,ah3, bh0,bh1);
            MMA(acc[2*ntp],   ah0,ah1,ah2,ah3, bl0,bl1);
            MMA(acc[2*ntp],   al0,al1,al2,al3, bh0,bh1);
            MMA(acc[2*ntp+1], ah0,ah1,ah2,ah3, bh2,bh3);
            MMA(acc[2*ntp+1], ah0,ah1,ah2,ah3, bl2,bl3);
            MMA(acc[2*ntp+1], al0,al1,al2,al3, bh2,bh3);
        }
    }

    // ---- epilogue: scale + bias + mask, softmax over each row ----
    {
        const float* bt = (const float*)(smem + SM_BIAS);
        const bool dm = (w == 127);
        float mlo = -1e30f, mhi = -1e30f;
        #pragma unroll
        for (int nt = 0; nt < 8; ++nt) {
            int c0 = nt * 8 + 2 * t;
            float b0v = bt[r_lo - c0 + 63], b1v = bt[r_lo - c0 + 62];
            float b2v = bt[r_hi - c0 + 63], b3v = bt[r_hi - c0 + 62];
            float mk_lo = (dm && ((r_lo < 32) != (c0 < 32))) ? -100.0f : 0.0f;
            float mk_hi = (dm && ((r_hi < 32) != (c0 < 32))) ? -100.0f : 0.0f;
            acc[nt][0] = acc[nt][0] * 0.125f + b0v + mk_lo;
            acc[nt][1] = acc[nt][1] * 0.125f + b1v + mk_lo;
            acc[nt][2] = acc[nt][2] * 0.125f + b2v + mk_hi;
            acc[nt][3] = acc[nt][3] * 0.125f + b3v + mk_hi;
            mlo = fmaxf(mlo, fmaxf(acc[nt][0], acc[nt][1]));
            mhi = fmaxf(mhi, fmaxf(acc[nt][2], acc[nt][3]));
        }
        mlo = fmaxf(mlo, __shfl_xor_sync(0xffffffffu, mlo, 1));
        mlo = fmaxf(mlo, __shfl_xor_sync(0xffffffffu, mlo, 2));
        mhi = fmaxf(mhi, __shfl_xor_sync(0xffffffffu, mhi, 1));
        mhi = fmaxf(mhi, __shfl_xor_sync(0xffffffffu, mhi, 2));
        float slo = 0.0f, shi = 0.0f;
        #pragma unroll
        for (int nt = 0; nt < 8; ++nt) {
            acc[nt][0] = __expf(acc[nt][0] - mlo);
            acc[nt][1] = __expf(acc[nt][1] - mlo);
            acc[nt][2] = __expf(acc[nt][2] - mhi);
            acc[nt][3] = __expf(acc[nt][3] - mhi);
            slo += acc[nt][0] + acc[nt][1];
            shi += acc[nt][2] + acc[nt][3];
        }
        slo += __shfl_xor_sync(0xffffffffu, slo, 1);
        slo += __shfl_xor_sync(0xffffffffu, slo, 2);
        shi += __shfl_xor_sync(0xffffffffu, shi, 1);
        shi += __shfl_xor_sync(0xffffffffu, shi, 2);
        float ilo = __fdividef(1.0f, slo), ihi = __fdividef(1.0f, shi);
        #pragma unroll
        for (int nt = 0; nt < 8; ++nt) {
            acc[nt][0] *= ilo; acc[nt][1] *= ilo;
            acc[nt][2] *= ihi; acc[nt][3] *= ihi;
        }
    }

    // ---- write attn ----
    {
        float* oat = out + 16777216L + (long)g * 4096;
        #pragma unroll
        for (int nt = 0; nt < 8; ++nt) {
            int c0 = nt * 8 + 2 * t;
            *(float2*)(oat + r_lo * 64 + c0) = make_float2(acc[nt][0], acc[nt][1]);
            *(float2*)(oat + r_hi * 64 + c0) = make_float2(acc[nt][2], acc[nt][3]);
        }
    }

    // ---- convert P (in acc) directly into gemm2 A-fragments ----
    uint32_t pah[16], pal[16];
    #pragma unroll
    for (int kc = 0; kc < 4; ++kc) {
        split2(acc[2*kc][0],   acc[2*kc][1],   pah[kc*4+0], pal[kc*4+0]);
        split2(acc[2*kc][2],   acc[2*kc][3],   pah[kc*4+1], pal[kc*4+1]);
        split2(acc[2*kc+1][0], acc[2*kc+1][1], pah[kc*4+2], pal[kc*4+2]);
        split2(acc[2*kc+1][2], acc[2*kc+1][3], pah[kc*4+3], pal[kc*4+3]);
    }

    // ---- gemm2: O = P V (hh + hl + lh), V via ldmatrix.trans ----
    #pragma unroll
    for (int nt = 0; nt < 8; ++nt)
        #pragma unroll
        for (int e = 0; e < 4; ++e) acc[nt][e] = 0.0f;

    #pragma unroll
    for (int kc = 0; kc < 4; ++kc) {
        uint32_t ah0 = pah[kc*4+0], ah1 = pah[kc*4+1], ah2 = pah[kc*4+2], ah3 = pah[kc*4+3];
        uint32_t al0 = pal[kc*4+0], al1 = pal[kc*4+1], al2 = pal[kc*4+2], al3 = pal[kc*4+3];
        uint32_t grp = (uint32_t)(lane >> 3), l8 = (uint32_t)(lane & 7);
        uint32_t krow = (uint32_t)kc * 16 + ((grp & 1) << 3) + l8;
        uint32_t nbase = ((grp >> 1) << 3);
        #pragma unroll
        for (int ntp = 0; ntp < 4; ++ntp) {
            uint32_t boff = SWZ(krow * 128 + (nbase + ntp * 16) * 2);
            uint32_t bh0,bh1,bh2,bh3, bl0,bl1,bl2,bl3;
            LDSM_X4_T(bh0,bh1,bh2,bh3, sb + SM_VH + boff);
            LDSM_X4_T(bl0,bl1,bl2,bl3, sb + SM_VL + boff);
            MMA(acc[2*ntp],   ah0,ah1,ah2,ah3, bh0,bh1);
            MMA(acc[2*ntp],   ah0,ah1,ah2,ah3, bl0,bl1);
            MMA(acc[2*ntp],   al0,al1,al2,al3, bh0,bh1);
            MMA(acc[2*ntp+1], ah0,ah1,ah2,ah3, bh2,bh3);
            MMA(acc[2*ntp+1], ah0,ah1,ah2,ah3, bl2,bl3);
            MMA(acc[2*ntp+1], al0,al1,al2,al3, bh2,bh3);
        }
    }

    // ---- write x with inverse cyclic shift ----
    {
        int row_lo = (start + r_lo) & 8191;
        int row_hi = (start + r_hi) & 8191;
        float* op_lo = out + (batch_base + row_lo) * 64;
        float* op_hi = out + (batch_base + row_hi) * 64;
        #pragma unroll
        for (int nt = 0; nt < 8; ++nt) {
            int c0 = nt * 8 + 2 * t;
            *(float2*)(op_lo + c0) = make_float2(acc[nt][0], acc[nt][1]);
            *(float2*)(op_hi + c0) = make_float2(acc[nt][2], acc[nt][3]);
        }
    }
}

extern "C" void kernel_launch(void* const* d_in, const int* in_sizes, int n_in,
                              void* d_out, int out_size)
{
    const float* q   = (const float*)d_in[0];
    const float* k   = (const float*)d_in[1];
    const float* v   = (const float*)d_in[2];
    const float* tab = (const float*)d_in[3];
    float* out = (float*)d_out;
    (void)in_sizes; (void)n_in; (void)out_size;

    cudaFuncSetAttribute(win_attn_mma,
                         cudaFuncAttributeMaxDynamicSharedMemorySize, SM_TOTAL);
    win_attn_mma<<<NBLK, TPB, SM_TOTAL>>>(q, k, v, tab, out);
}

// round 11
// speedup vs baseline: 1.2536x; 1.1450x over previous
#include <cuda_runtime.h>
#include <cuda_bf16.h>
#include <cstdint>

// Shifted-window attention via warp-level bf16 mma.sync (m16n8k16), hi/lo
// 3-product split. One CTA (128 thr) per window; warp owns 16 rows.
// Q direct global->regs (warp-private A-frags); P kept in registers
// (acc layout == A-frag layout). Smem only for K and V hi/lo tiles.
// 5 CTAs/SM (96 regs, no spills) — 6-CTA cap spills and regresses.

#define TPB 128
#define NBLK 4096

#define SM_KH 0
#define SM_KL 8192
#define SM_VH 16384
#define SM_VL 24576
#define SM_BIAS 32768    // 127 floats
#define SM_TOTAL 33408

#define SWZ(x) ((x) ^ (((x) >> 3) & 0x70))

__device__ __forceinline__ uint32_t smem_u32(const void* p){
    uint32_t a;
    asm("{ .reg .u64 t; cvta.to.shared.u64 t, %1; cvt.u32.u64 %0, t; }" : "=r"(a) : "l"(p));
    return a;
}
// pack floats a(lo half),b(hi half) to bf16x2 hi-part and residual lo-part
__device__ __forceinline__ void split2(float a, float b, uint32_t& hi, uint32_t& lo){
    uint32_t h;
    asm("cvt.rn.bf16x2.f32 %0, %1, %2;" : "=r"(h) : "f"(b), "f"(a));
    float ha = __uint_as_float(h << 16);
    float hb = __uint_as_float(h & 0xffff0000u);
    uint32_t l;
    asm("cvt.rn.bf16x2.f32 %0, %1, %2;" : "=r"(l) : "f"(b - hb), "f"(a - ha));
    hi = h; lo = l;
}
#define LDSM_X4(r0,r1,r2,r3, a) \
    asm volatile("ldmatrix.sync.aligned.m8n8.x4.shared.b16 {%0,%1,%2,%3}, [%4];" \
        : "=r"(r0),"=r"(r1),"=r"(r2),"=r"(r3) : "r"(a))
#define LDSM_X4_T(r0,r1,r2,r3, a) \
    asm volatile("ldmatrix.sync.aligned.m8n8.x4.trans.shared.b16 {%0,%1,%2,%3}, [%4];" \
        : "=r"(r0),"=r"(r1),"=r"(r2),"=r"(r3) : "r"(a))
#define MMA(d, a0,a1,a2,a3, b0,b1) \
    asm volatile("mma.sync.aligned.m16n8k16.row.col.f32.bf16.bf16.f32 " \
        "{%0,%1,%2,%3}, {%4,%5,%6,%7}, {%8,%9}, {%0,%1,%2,%3};" \
        : "+f"((d)[0]),"+f"((d)[1]),"+f"((d)[2]),"+f"((d)[3]) \
        : "r"(a0),"r"(a1),"r"(a2),"r"(a3), "r"(b0),"r"(b1))

extern "C" __global__ void __launch_bounds__(TPB, 5)
win_attn_mma(const float* __restrict__ q, const float* __restrict__ k,
             const float* __restrict__ v, const float* __restrict__ tab,
             float* __restrict__ out)
{
    extern __shared__ __align__(128) char smem[];
    const uint32_t sb = smem_u32(smem);
    const int tid = threadIdx.x;
    const int g   = blockIdx.x;
    const int bb  = g >> 7;          // batch
    const int w   = g & 127;         // window
    const int start = w * 64 + 32;   // cyclic shift by -32 as gather
    const long batch_base = (long)bb * 8192;

    // ---- load K,V window: fp32 -> bf16 hi/lo, 16B swizzled stores ----
    // thread handles 8 consecutive cols of one row per iter
    #pragma unroll
    for (int it = 0; it < 4; ++it) {
        int idx = it * TPB + tid;        // 0..511
        int p = idx >> 3, c8 = idx & 7;  // row p, cols 8c8..8c8+7
        int row = (start + p) & 8191;
        long go = (batch_base + row) * 64 + c8 * 8;
        uint32_t so = SWZ((uint32_t)(p * 128 + c8 * 16));
        float4 ka = *(const float4*)(k + go);
        float4 kb = *(const float4*)(k + go + 4);
        float4 va = *(const float4*)(v + go);
        float4 vb = *(const float4*)(v + go + 4);
        uint32_t h0,l0,h1,l1,h2,l2,h3,l3;
        split2(ka.x, ka.y, h0, l0); split2(ka.z, ka.w, h1, l1);
        split2(kb.x, kb.y, h2, l2); split2(kb.z, kb.w, h3, l3);
        *(uint4*)(smem + SM_KH + so) = make_uint4(h0, h1, h2, h3);
        *(uint4*)(smem + SM_KL + so) = make_uint4(l0, l1, l2, l3);
        split2(va.x, va.y, h0, l0); split2(va.z, va.w, h1, l1);
        split2(vb.x, vb.y, h2, l2); split2(vb.z, vb.w, h3, l3);
        *(uint4*)(smem + SM_VH + so) = make_uint4(h0, h1, h2, h3);
        *(uint4*)(smem + SM_VL + so) = make_uint4(l0, l1, l2, l3);
    }
    if (tid < 127) ((float*)(smem + SM_BIAS))[tid] = tab[tid];

    const int wid  = tid >> 5, lane = tid & 31;
    const int gq   = lane >> 2, t = lane & 3;
    const int R0   = wid * 16;
    const int r_lo = R0 + gq, r_hi = r_lo + 8;

    // ---- Q A-fragments: direct global loads (warp-private rows) ----
    const float* qlo = q + (batch_base + ((start + r_lo) & 8191)) * 64 + 2 * t;
    const float* qhi = q + (batch_base + ((start + r_hi) & 8191)) * 64 + 2 * t;
    uint32_t qah[16], qal[16];   // [kc*4 + {a0,a1,a2,a3}]
    #pragma unroll
    for (int kc = 0; kc < 4; ++kc) {
        float2 f0 = *(const float2*)(qlo + kc * 16);
        float2 f1 = *(const float2*)(qhi + kc * 16);
        float2 f2 = *(const float2*)(qlo + kc * 16 + 8);
        float2 f3 = *(const float2*)(qhi + kc * 16 + 8);
        split2(f0.x, f0.y, qah[kc*4+0], qal[kc*4+0]);
        split2(f1.x, f1.y, qah[kc*4+1], qal[kc*4+1]);
        split2(f2.x, f2.y, qah[kc*4+2], qal[kc*4+2]);
        split2(f3.x, f3.y, qah[kc*4+3], qal[kc*4+3]);
    }
    __syncthreads();

    float acc[8][4];
    #pragma unroll
    for (int nt = 0; nt < 8; ++nt)
        #pragma unroll
        for (int e = 0; e < 4; ++e) acc[nt][e] = 0.0f;

    // ---- gemm1: S = Q K^T (hh + hl + lh) ----
    #pragma unroll
    for (int kc = 0; kc < 4; ++kc) {
        uint32_t ah0 = qah[kc*4+0], ah1 = qah[kc*4+1], ah2 = qah[kc*4+2], ah3 = qah[kc*4+3];
        uint32_t al0 = qal[kc*4+0], al1 = qal[kc*4+1], al2 = qal[kc*4+2], al3 = qal[kc*4+3];
        uint32_t grp = (uint32_t)(lane >> 3), l8 = (uint32_t)(lane & 7);
        uint32_t nrow_b = ((grp >> 1) << 3) + l8;
        uint32_t kcol_b = (uint32_t)kc * 32 + ((grp & 1) << 4);
        #pragma unroll
        for (int ntp = 0; ntp < 4; ++ntp) {
            uint32_t boff = SWZ((nrow_b + ntp * 16) * 128 + kcol_b);
            uint32_t bh0,bh1,bh2,bh3, bl0,bl1,bl2,bl3;
            LDSM_X4(bh0,bh1,bh2,bh3, sb + SM_KH + boff);
            LDSM_X4(bl0,bl1,bl2,bl3, sb + SM_KL + boff);
            MMA(acc[2*ntp],   ah0,ah1,ah2,ah3, bh0,bh1);
            MMA(acc[2*ntp],   ah0,ah1,ah2,ah3, bl0,bl1);
            MMA(acc[2*ntp],   al0,al1,al2,al3, bh0,bh1);
            MMA(acc[2*ntp+1], ah0,ah1,ah2,ah3, bh2,bh3);
            MMA(acc[2*ntp+1], ah0,ah1,ah2,ah3, bl2,bl3);
            MMA(acc[2*ntp+1], al0,al1,al2,al3, bh2,bh3);
        }
    }

    // ---- epilogue: scale + bias + mask, softmax over each row ----
    {
        const float* bt = (const float*)(smem + SM_BIAS);
        const bool dm = (w == 127);
        float mlo = -1e30f, mhi = -1e30f;
        #pragma unroll
        for (int nt = 0; nt < 8; ++nt) {
            int c0 = nt * 8 + 2 * t;
            float b0v = bt[r_lo - c0 + 63], b1v = bt[r_lo - c0 + 62];
            float b2v = bt[r_hi - c0 + 63], b3v = bt[r_hi - c0 + 62];
            float mk_lo = (dm && ((r_lo < 32) != (c0 < 32))) ? -100.0f : 0.0f;
            float mk_hi = (dm && ((r_hi < 32) != (c0 < 32))) ? -100.0f : 0.0f;
            acc[nt][0] = acc[nt][0] * 0.125f + b0v + mk_lo;
            acc[nt][1] = acc[nt][1] * 0.125f + b1v + mk_lo;
            acc[nt][2] = acc[nt][2] * 0.125f + b2v + mk_hi;
            acc[nt][3] = acc[nt][3] * 0.125f + b3v + mk_hi;
            mlo = fmaxf(mlo, fmaxf(acc[nt][0], acc[nt][1]));
            mhi = fmaxf(mhi, fmaxf(acc[nt][2], acc[nt][3]));
        }
        mlo = fmaxf(mlo, __shfl_xor_sync(0xffffffffu, mlo, 1));
        mlo = fmaxf(mlo, __shfl_xor_sync(0xffffffffu, mlo, 2));
        mhi = fmaxf(mhi, __shfl_xor_sync(0xffffffffu, mhi, 1));
        mhi = fmaxf(mhi, __shfl_xor_sync(0xffffffffu, mhi, 2));
        float slo = 0.0f, shi = 0.0f;
        #pragma unroll
        for (int nt = 0; nt < 8; ++nt) {
            acc[nt][0] = __expf(acc[nt][0] - mlo);
            acc[nt][1] = __expf(acc[nt][1] - mlo);
            acc[nt][2] = __expf(acc[nt][2] - mhi);
            acc[nt][3] = __expf(acc[nt][3] - mhi);
            slo += acc[nt][0] + acc[nt][1];
            shi += acc[nt][2] + acc[nt][3];
        }
        slo += __shfl_xor_sync(0xffffffffu, slo, 1);
        slo += __shfl_xor_sync(0xffffffffu, slo, 2);
        shi += __shfl_xor_sync(0xffffffffu, shi, 1);
        shi += __shfl_xor_sync(0xffffffffu, shi, 2);
        float ilo = __fdividef(1.0f, slo), ihi = __fdividef(1.0f, shi);
        #pragma unroll
        for (int nt = 0; nt < 8; ++nt) {
            acc[nt][0] *= ilo; acc[nt][1] *= ilo;
            acc[nt][2] *= ihi; acc[nt][3] *= ihi;
        }
    }

    // ---- write attn ----
    {
        float* oat = out + 16777216L + (long)g * 4096;
        #pragma unroll
        for (int nt = 0; nt < 8; ++nt) {
            int c0 = nt * 8 + 2 * t;
            *(float2*)(oat + r_lo * 64 + c0) = make_float2(acc[nt][0], acc[nt][1]);
            *(float2*)(oat + r_hi * 64 + c0) = make_float2(acc[nt][2], acc[nt][3]);
        }
    }

    // ---- convert P (in acc) directly into gemm2 A-fragments ----
    uint32_t pah[16], pal[16];
    #pragma unroll
    for (int kc = 0; kc < 4; ++kc) {
        split2(acc[2*kc][0],   acc[2*kc][1],   pah[kc*4+0], pal[kc*4+0]);
        split2(acc[2*kc][2],   acc[2*kc][3],   pah[kc*4+1], pal[kc*4+1]);
        split2(acc[2*kc+1][0], acc[2*kc+1][1], pah[kc*4+2], pal[kc*4+2]);
        split2(acc[2*kc+1][2], acc[2*kc+1][3], pah[kc*4+3], pal[kc*4+3]);
    }

    // ---- gemm2: O = P V (hh + hl + lh), V via ldmatrix.trans ----
    #pragma unroll
    for (int nt = 0; nt < 8; ++nt)
        #pragma unroll
        for (int e = 0; e < 4; ++e) acc[nt][e] = 0.0f;

    #pragma unroll
    for (int kc = 0; kc < 4; ++kc) {
        uint32_t ah0 = pah[kc*4+0], ah1 = pah[kc*4+1], ah2 = pah[kc*4+2], ah3 = pah[kc*4+3];
        uint32_t al0 = pal[kc*4+0], al1 = pal[kc*4+1], al2 = pal[kc*4+2], al3 = pal[kc*4+3];
        uint32_t grp = (uint32_t)(lane >> 3), l8 = (uint32_t)(lane & 7);
        uint32_t krow = (uint32_t)kc * 16 + ((grp & 1) << 3) + l8;
        uint32_t nbase = ((grp >> 1) << 3);
        #pragma unroll
        for (int ntp = 0; ntp < 4; ++ntp) {
            uint32_t boff = SWZ(krow * 128 + (nbase + ntp * 16) * 2);
            uint32_t bh0,bh1,bh2,bh3, bl0,bl1,bl2,bl3;
            LDSM_X4_T(bh0,bh1,bh2,bh3, sb + SM_VH + boff);
            LDSM_X4_T(bl0,bl1,bl2,bl3, sb + SM_VL + boff);
            MMA(acc[2*ntp],   ah0,ah1,ah2,ah3, bh0,bh1);
            MMA(acc[2*ntp],   ah0,ah1,ah2,ah3, bl0,bl1);
            MMA(acc[2*ntp],   al0,al1,al2,al3, bh0,bh1);
            MMA(acc[2*ntp+1], ah0,ah1,ah2,ah3, bh2,bh3);
            MMA(acc[2*ntp+1], ah0,ah1,ah2,ah3, bl2,bl3);
            MMA(acc[2*ntp+1], al0,al1,al2,al3, bh2,bh3);
        }
    }

    // ---- write x with inverse cyclic shift ----
    {
        int row_lo = (start + r_lo) & 8191;
        int row_hi = (start + r_hi) & 8191;
        float* op_lo = out + (batch_base + row_lo) * 64;
        float* op_hi = out + (batch_base + row_hi) * 64;
        #pragma unroll
        for (int nt = 0; nt < 8; ++nt) {
            int c0 = nt * 8 + 2 * t;
            *(float2*)(op_lo + c0) = make_float2(acc[nt][0], acc[nt][1]);
            *(float2*)(op_hi + c0) = make_float2(acc[nt][2], acc[nt][3]);
        }
    }
}

extern "C" void kernel_launch(void* const* d_in, const int* in_sizes, int n_in,
                              void* d_out, int out_size)
{
    const float* q   = (const float*)d_in[0];
    const float* k   = (const float*)d_in[1];
    const float* v   = (const float*)d_in[2];
    const float* tab = (const float*)d_in[3];
    float* out = (float*)d_out;
    (void)in_sizes; (void)n_in; (void)out_size;

    cudaFuncSetAttribute(win_attn_mma,
                         cudaFuncAttributeMaxDynamicSharedMemorySize, SM_TOTAL);
    win_attn_mma<<<NBLK, TPB, SM_TOTAL>>>(q, k, v, tab, out);
}

// round 12
// speedup vs baseline: 1.3962x; 1.1137x over previous
#include <cuda_runtime.h>
#include <cuda_fp16.h>
#include <cstdint>

// Shifted-window attention via warp-level fp16 mma.sync (m16n8k16).
// A-side (Q, P) split hi/lo in fp16; B-side (K, V) single fp16 tile
// (fp16's 11 mantissa bits keep rel err ~2e-4 << 1e-3 tolerance).
// One CTA (128 thr) per window; warp owns 16 rows; Q direct global->regs;
// P kept in registers (acc layout == A-frag layout). 5 CTAs/SM, 96 regs.

#define TPB 128
#define NBLK 4096

#define SM_KH 0          // K fp16 tile, 64 rows x 128B
#define SM_VH 8192       // V fp16 tile
#define SM_BIAS 16384    // 127 floats
#define SM_TOTAL 16896

#define SWZ(x) ((x) ^ (((x) >> 3) & 0x70))

__device__ __forceinline__ uint32_t smem_u32(const void* p){
    uint32_t a;
    asm("{ .reg .u64 t; cvta.to.shared.u64 t, %1; cvt.u32.u64 %0, t; }" : "=r"(a) : "l"(p));
    return a;
}
// pack two floats into one f16x2 register: {lo half = a, hi half = b}
__device__ __forceinline__ uint32_t pk16(float a, float b){
    uint32_t h;
    asm("cvt.rn.f16x2.f32 %0, %1, %2;" : "=r"(h) : "f"(b), "f"(a));
    return h;
}
// fp16 hi/lo split of (a,b): hi = rn(a,b) packed, lo = rn(a-hi.a, b-hi.b)
__device__ __forceinline__ void split2h(float a, float b, uint32_t& hi, uint32_t& lo){
    uint32_t h;
    asm("cvt.rn.f16x2.f32 %0, %1, %2;" : "=r"(h) : "f"(b), "f"(a));
    float ha, hb;
    asm("{ .reg .b16 x, y; mov.b32 {x, y}, %2; cvt.f32.f16 %0, x; cvt.f32.f16 %1, y; }"
        : "=f"(ha), "=f"(hb) : "r"(h));
    uint32_t l;
    asm("cvt.rn.f16x2.f32 %0, %1, %2;" : "=r"(l) : "f"(b - hb), "f"(a - ha));
    hi = h; lo = l;
}
#define LDSM_X4(r0,r1,r2,r3, a) \
    asm volatile("ldmatrix.sync.aligned.m8n8.x4.shared.b16 {%0,%1,%2,%3}, [%4];" \
        : "=r"(r0),"=r"(r1),"=r"(r2),"=r"(r3) : "r"(a))
#define LDSM_X4_T(r0,r1,r2,r3, a) \
    asm volatile("ldmatrix.sync.aligned.m8n8.x4.trans.shared.b16 {%0,%1,%2,%3}, [%4];" \
        : "=r"(r0),"=r"(r1),"=r"(r2),"=r"(r3) : "r"(a))
#define MMA(d, a0,a1,a2,a3, b0,b1) \
    asm volatile("mma.sync.aligned.m16n8k16.row.col.f32.f16.f16.f32 " \
        "{%0,%1,%2,%3}, {%4,%5,%6,%7}, {%8,%9}, {%0,%1,%2,%3};" \
        : "+f"((d)[0]),"+f"((d)[1]),"+f"((d)[2]),"+f"((d)[3]) \
        : "r"(a0),"r"(a1),"r"(a2),"r"(a3), "r"(b0),"r"(b1))

extern "C" __global__ void __launch_bounds__(TPB, 5)
win_attn_mma(const float* __restrict__ q, const float* __restrict__ k,
             const float* __restrict__ v, const float* __restrict__ tab,
             float* __restrict__ out)
{
    extern __shared__ __align__(128) char smem[];
    const uint32_t sb = smem_u32(smem);
    const int tid = threadIdx.x;
    const int g   = blockIdx.x;
    const int bb  = g >> 7;          // batch
    const int w   = g & 127;         // window
    const int start = w * 64 + 32;   // cyclic shift by -32 as gather
    const long batch_base = (long)bb * 8192;

    // ---- load K,V window: fp32 -> fp16 single, 16B swizzled stores ----
    #pragma unroll
    for (int it = 0; it < 4; ++it) {
        int idx = it * TPB + tid;        // 0..511
        int p = idx >> 3, c8 = idx & 7;  // row p, cols 8c8..8c8+7
        int row = (start + p) & 8191;
        long go = (batch_base + row) * 64 + c8 * 8;
        uint32_t so = SWZ((uint32_t)(p * 128 + c8 * 16));
        float4 ka = *(const float4*)(k + go);
        float4 kb = *(const float4*)(k + go + 4);
        float4 va = *(const float4*)(v + go);
        float4 vb = *(const float4*)(v + go + 4);
        *(uint4*)(smem + SM_KH + so) =
            make_uint4(pk16(ka.x, ka.y), pk16(ka.z, ka.w), pk16(kb.x, kb.y), pk16(kb.z, kb.w));
        *(uint4*)(smem + SM_VH + so) =
            make_uint4(pk16(va.x, va.y), pk16(va.z, va.w), pk16(vb.x, vb.y), pk16(vb.z, vb.w));
    }
    if (tid < 127) ((float*)(smem + SM_BIAS))[tid] = tab[tid];

    const int wid  = tid >> 5, lane = tid & 31;
    const int gq   = lane >> 2, t = lane & 3;
    const int R0   = wid * 16;
    const int r_lo = R0 + gq, r_hi = r_lo + 8;

    // ---- Q A-fragments: direct global loads, fp16 hi/lo split ----
    const float* qlo = q + (batch_base + ((start + r_lo) & 8191)) * 64 + 2 * t;
    const float* qhi = q + (batch_base + ((start + r_hi) & 8191)) * 64 + 2 * t;
    uint32_t qah[16], qal[16];   // [kc*4 + {a0,a1,a2,a3}]
    #pragma unroll
    for (int kc = 0; kc < 4; ++kc) {
        float2 f0 = *(const float2*)(qlo + kc * 16);
        float2 f1 = *(const float2*)(qhi + kc * 16);
        float2 f2 = *(const float2*)(qlo + kc * 16 + 8);
        float2 f3 = *(const float2*)(qhi + kc * 16 + 8);
        split2h(f0.x, f0.y, qah[kc*4+0], qal[kc*4+0]);
        split2h(f1.x, f1.y, qah[kc*4+1], qal[kc*4+1]);
        split2h(f2.x, f2.y, qah[kc*4+2], qal[kc*4+2]);
        split2h(f3.x, f3.y, qah[kc*4+3], qal[kc*4+3]);
    }
    __syncthreads();

    float acc[8][4];
    #pragma unroll
    for (int nt = 0; nt < 8; ++nt)
        #pragma unroll
        for (int e = 0; e < 4; ++e) acc[nt][e] = 0.0f;

    // ---- gemm1: S = (Qh + Ql) K^T,  K single fp16 ----
    #pragma unroll
    for (int kc = 0; kc < 4; ++kc) {
        uint32_t ah0 = qah[kc*4+0], ah1 = qah[kc*4+1], ah2 = qah[kc*4+2], ah3 = qah[kc*4+3];
        uint32_t al0 = qal[kc*4+0], al1 = qal[kc*4+1], al2 = qal[kc*4+2], al3 = qal[kc*4+3];
        uint32_t grp = (uint32_t)(lane >> 3), l8 = (uint32_t)(lane & 7);
        uint32_t nrow_b = ((grp >> 1) << 3) + l8;
        uint32_t kcol_b = (uint32_t)kc * 32 + ((grp & 1) << 4);
        #pragma unroll
        for (int ntp = 0; ntp < 4; ++ntp) {
            uint32_t boff = SWZ((nrow_b + ntp * 16) * 128 + kcol_b);
            uint32_t bh0,bh1,bh2,bh3;
            LDSM_X4(bh0,bh1,bh2,bh3, sb + SM_KH + boff);
            MMA(acc[2*ntp],   ah0,ah1,ah2,ah3, bh0,bh1);
            MMA(acc[2*ntp],   al0,al1,al2,al3, bh0,bh1);
            MMA(acc[2*ntp+1], ah0,ah1,ah2,ah3, bh2,bh3);
            MMA(acc[2*ntp+1], al0,al1,al2,al3, bh2,bh3);
        }
    }

    // ---- epilogue: scale + bias + mask, softmax over each row ----
    {
        const float* bt = (const float*)(smem + SM_BIAS);
        const bool dm = (w == 127);
        float mlo = -1e30f, mhi = -1e30f;
        #pragma unroll
        for (int nt = 0; nt < 8; ++nt) {
            int c0 = nt * 8 + 2 * t;
            float b0v = bt[r_lo - c0 + 63], b1v = bt[r_lo - c0 + 62];
            float b2v = bt[r_hi - c0 + 63], b3v = bt[r_hi - c0 + 62];
            float mk_lo = (dm && ((r_lo < 32) != (c0 < 32))) ? -100.0f : 0.0f;
            float mk_hi = (dm && ((r_hi < 32) != (c0 < 32))) ? -100.0f : 0.0f;
            acc[nt][0] = acc[nt][0] * 0.125f + b0v + mk_lo;
            acc[nt][1] = acc[nt][1] * 0.125f + b1v + mk_lo;
            acc[nt][2] = acc[nt][2] * 0.125f + b2v + mk_hi;
            acc[nt][3] = acc[nt][3] * 0.125f + b3v + mk_hi;
            mlo = fmaxf(mlo, fmaxf(acc[nt][0], acc[nt][1]));
            mhi = fmaxf(mhi, fmaxf(acc[nt][2], acc[nt][3]));
        }
        mlo = fmaxf(mlo, __shfl_xor_sync(0xffffffffu, mlo, 1));
        mlo = fmaxf(mlo, __shfl_xor_sync(0xffffffffu, mlo, 2));
        mhi = fmaxf(mhi, __shfl_xor_sync(0xffffffffu, mhi, 1));
        mhi = fmaxf(mhi, __shfl_xor_sync(0xffffffffu, mhi, 2));
        float slo = 0.0f, shi = 0.0f;
        #pragma unroll
        for (int nt = 0; nt < 8; ++nt) {
            acc[nt][0] = __expf(acc[nt][0] - mlo);
            acc[nt][1] = __expf(acc[nt][1] - mlo);
            acc[nt][2] = __expf(acc[nt][2] - mhi);
            acc[nt][3] = __expf(acc[nt][3] - mhi);
            slo += acc[nt][0] + acc[nt][1];
            shi += acc[nt][2] + acc[nt][3];
        }
        slo += __shfl_xor_sync(0xffffffffu, slo, 1);
        slo += __shfl_xor_sync(0xffffffffu, slo, 2);
        shi += __shfl_xor_sync(0xffffffffu, shi, 1);
        shi += __shfl_xor_sync(0xffffffffu, shi, 2);
        float ilo = __fdividef(1.0f, slo), ihi = __fdividef(1.0f, shi);
        #pragma unroll
        for (int nt = 0; nt < 8; ++nt) {
            acc[nt][0] *= ilo; acc[nt][1] *= ilo;
            acc[nt][2] *= ihi; acc[nt][3] *= ihi;
        }
    }

    // ---- write attn ----
    {
        float* oat = out + 16777216L + (long)g * 4096;
        #pragma unroll
        for (int nt = 0; nt < 8; ++nt) {
            int c0 = nt * 8 + 2 * t;
            *(float2*)(oat + r_lo * 64 + c0) = make_float2(acc[nt][0], acc[nt][1]);
            *(float2*)(oat + r_hi * 64 + c0) = make_float2(acc[nt][2], acc[nt][3]);
        }
    }

    // ---- convert P (in acc) directly into gemm2 A-fragments (fp16 hi/lo) ----
    uint32_t pah[16], pal[16];
    #pragma unroll
    for (int kc = 0; kc < 4; ++kc) {
        split2h(acc[2*kc][0],   acc[2*kc][1],   pah[kc*4+0], pal[kc*4+0]);
        split2h(acc[2*kc][2],   acc[2*kc][3],   pah[kc*4+1], pal[kc*4+1]);
        split2h(acc[2*kc+1][0], acc[2*kc+1][1], pah[kc*4+2], pal[kc*4+2]);
        split2h(acc[2*kc+1][2], acc[2*kc+1][3], pah[kc*4+3], pal[kc*4+3]);
    }

    // ---- gemm2: O = (Ph + Pl) V,  V single fp16 via ldmatrix.trans ----
    #pragma unroll
    for (int nt = 0; nt < 8; ++nt)
        #pragma unroll
        for (int e = 0; e < 4; ++e) acc[nt][e] = 0.0f;

    #pragma unroll
    for (int kc = 0; kc < 4; ++kc) {
        uint32_t ah0 = pah[kc*4+0], ah1 = pah[kc*4+1], ah2 = pah[kc*4+2], ah3 = pah[kc*4+3];
        uint32_t al0 = pal[kc*4+0], al1 = pal[kc*4+1], al2 = pal[kc*4+2], al3 = pal[kc*4+3];
        uint32_t grp = (uint32_t)(lane >> 3), l8 = (uint32_t)(lane & 7);
        uint32_t krow = (uint32_t)kc * 16 + ((grp & 1) << 3) + l8;
        uint32_t nbase = ((grp >> 1) << 3);
        #pragma unroll
        for (int ntp = 0; ntp < 4; ++ntp) {
            uint32_t boff = SWZ(krow * 128 + (nbase + ntp * 16) * 2);
            uint32_t bh0,bh1,bh2,bh3;
            LDSM_X4_T(bh0,bh1,bh2,bh3, sb + SM_VH + boff);
            MMA(acc[2*ntp],   ah0,ah1,ah2,ah3, bh0,bh1);
            MMA(acc[2*ntp],   al0,al1,al2,al3, bh0,bh1);
            MMA(acc[2*ntp+1], ah0,ah1,ah2,ah3, bh2,bh3);
            MMA(acc[2*ntp+1], al0,al1,al2,al3, bh2,bh3);
        }
    }

    // ---- write x with inverse cyclic shift ----
    {
        int row_lo = (start + r_lo) & 8191;
        int row_hi = (start + r_hi) & 8191;
        float* op_lo = out + (batch_base + row_lo) * 64;
        float* op_hi = out + (batch_base + row_hi) * 64;
        #pragma unroll
        for (int nt = 0; nt < 8; ++nt) {
            int c0 = nt * 8 + 2 * t;
            *(float2*)(op_lo + c0) = make_float2(acc[nt][0], acc[nt][1]);
            *(float2*)(op_hi + c0) = make_float2(acc[nt][2], acc[nt][3]);
        }
    }
}

extern "C" void kernel_launch(void* const* d_in, const int* in_sizes, int n_in,
                              void* d_out, int out_size)
{
    const float* q   = (const float*)d_in[0];
    const float* k   = (const float*)d_in[1];
    const float* v   = (const float*)d_in[2];
    const float* tab = (const float*)d_in[3];
    float* out = (float*)d_out;
    (void)in_sizes; (void)n_in; (void)out_size;

    cudaFuncSetAttribute(win_attn_mma,
                         cudaFuncAttributeMaxDynamicSharedMemorySize, SM_TOTAL);
    win_attn_mma<<<NBLK, TPB, SM_TOTAL>>>(q, k, v, tab, out);
}

// round 14
// speedup vs baseline: 1.4357x; 1.0283x over previous
#include <cuda_runtime.h>
#include <cuda_fp16.h>
#include <cstdint>

// Shifted-window attention via warp-level fp16 mma.sync (m16n8k16).
// Q, K, V single fp16 (rounding err ~2.8e-4 each, quadrature ~4e-4 total);
// P split hi/lo in fp16 to protect x. One CTA (128 thr) per window; warp
// owns 16 rows; Q direct global->regs; P kept in registers. 6 CTAs/SM.

#define TPB 128
#define NBLK 4096

#define SM_KH 0          // K fp16 tile, 64 rows x 128B
#define SM_VH 8192       // V fp16 tile
#define SM_BIAS 16384    // 127 floats
#define SM_TOTAL 16896

#define SWZ(x) ((x) ^ (((x) >> 3) & 0x70))

__device__ __forceinline__ uint32_t smem_u32(const void* p){
    uint32_t a;
    asm("{ .reg .u64 t; cvta.to.shared.u64 t, %1; cvt.u32.u64 %0, t; }" : "=r"(a) : "l"(p));
    return a;
}
// pack two floats into one f16x2 register: {lo half = a, hi half = b}
__device__ __forceinline__ uint32_t pk16(float a, float b){
    uint32_t h;
    asm("cvt.rn.f16x2.f32 %0, %1, %2;" : "=r"(h) : "f"(b), "f"(a));
    return h;
}
// fp16 hi/lo split of (a,b): hi = rn(a,b) packed, lo = rn(a-hi.a, b-hi.b)
__device__ __forceinline__ void split2h(float a, float b, uint32_t& hi, uint32_t& lo){
    uint32_t h;
    asm("cvt.rn.f16x2.f32 %0, %1, %2;" : "=r"(h) : "f"(b), "f"(a));
    float ha, hb;
    asm("{ .reg .b16 x, y; mov.b32 {x, y}, %2; cvt.f32.f16 %0, x; cvt.f32.f16 %1, y; }"
        : "=f"(ha), "=f"(hb) : "r"(h));
    uint32_t l;
    asm("cvt.rn.f16x2.f32 %0, %1, %2;" : "=r"(l) : "f"(b - hb), "f"(a - ha));
    hi = h; lo = l;
}
#define LDSM_X4(r0,r1,r2,r3, a) \
    asm volatile("ldmatrix.sync.aligned.m8n8.x4.shared.b16 {%0,%1,%2,%3}, [%4];" \
        : "=r"(r0),"=r"(r1),"=r"(r2),"=r"(r3) : "r"(a))
#define LDSM_X4_T(r0,r1,r2,r3, a) \
    asm volatile("ldmatrix.sync.aligned.m8n8.x4.trans.shared.b16 {%0,%1,%2,%3}, [%4];" \
        : "=r"(r0),"=r"(r1),"=r"(r2),"=r"(r3) : "r"(a))
#define MMA(d, a0,a1,a2,a3, b0,b1) \
    asm volatile("mma.sync.aligned.m16n8k16.row.col.f32.f16.f16.f32 " \
        "{%0,%1,%2,%3}, {%4,%5,%6,%7}, {%8,%9}, {%0,%1,%2,%3};" \
        : "+f"((d)[0]),"+f"((d)[1]),"+f"((d)[2]),"+f"((d)[3]) \
        : "r"(a0),"r"(a1),"r"(a2),"r"(a3), "r"(b0),"r"(b1))

extern "C" __global__ void __launch_bounds__(TPB, 6)
win_attn_mma(const float* __restrict__ q, const float* __restrict__ k,
             const float* __restrict__ v, const float* __restrict__ tab,
             float* __restrict__ out)
{
    extern __shared__ __align__(128) char smem[];
    const uint32_t sb = smem_u32(smem);
    const int tid = threadIdx.x;
    const int g   = blockIdx.x;
    const int bb  = g >> 7;          // batch
    const int w   = g & 127;         // window
    const int start = w * 64 + 32;   // cyclic shift by -32 as gather
    const long batch_base = (long)bb * 8192;

    // ---- load K,V window: fp32 -> fp16, 16B swizzled stores ----
    #pragma unroll
    for (int it = 0; it < 4; ++it) {
        int idx = it * TPB + tid;        // 0..511
        int p = idx >> 3, c8 = idx & 7;  // row p, cols 8c8..8c8+7
        int row = (start + p) & 8191;
        long go = (batch_base + row) * 64 + c8 * 8;
        uint32_t so = SWZ((uint32_t)(p * 128 + c8 * 16));
        float4 ka = *(const float4*)(k + go);
        float4 kb = *(const float4*)(k + go + 4);
        float4 va = *(const float4*)(v + go);
        float4 vb = *(const float4*)(v + go + 4);
        *(uint4*)(smem + SM_KH + so) =
            make_uint4(pk16(ka.x, ka.y), pk16(ka.z, ka.w), pk16(kb.x, kb.y), pk16(kb.z, kb.w));
        *(uint4*)(smem + SM_VH + so) =
            make_uint4(pk16(va.x, va.y), pk16(va.z, va.w), pk16(vb.x, vb.y), pk16(vb.z, vb.w));
    }
    if (tid < 127) ((float*)(smem + SM_BIAS))[tid] = tab[tid];

    const int wid  = tid >> 5, lane = tid & 31;
    const int gq   = lane >> 2, t = lane & 3;
    const int R0   = wid * 16;
    const int r_lo = R0 + gq, r_hi = r_lo + 8;

    // ---- Q A-fragments: direct global loads, single fp16 ----
    const float* qlo = q + (batch_base + ((start + r_lo) & 8191)) * 64 + 2 * t;
    const float* qhi = q + (batch_base + ((start + r_hi) & 8191)) * 64 + 2 * t;
    uint32_t qah[16];   // [kc*4 + {a0,a1,a2,a3}]
    #pragma unroll
    for (int kc = 0; kc < 4; ++kc) {
        float2 f0 = *(const float2*)(qlo + kc * 16);
        float2 f1 = *(const float2*)(qhi + kc * 16);
        float2 f2 = *(const float2*)(qlo + kc * 16 + 8);
        float2 f3 = *(const float2*)(qhi + kc * 16 + 8);
        qah[kc*4+0] = pk16(f0.x, f0.y);
        qah[kc*4+1] = pk16(f1.x, f1.y);
        qah[kc*4+2] = pk16(f2.x, f2.y);
        qah[kc*4+3] = pk16(f3.x, f3.y);
    }
    __syncthreads();

    float acc[8][4];
    #pragma unroll
    for (int nt = 0; nt < 8; ++nt)
        #pragma unroll
        for (int e = 0; e < 4; ++e) acc[nt][e] = 0.0f;

    // ---- gemm1: S = Q K^T (single fp16 both sides) ----
    #pragma unroll
    for (int kc = 0; kc < 4; ++kc) {
        uint32_t ah0 = qah[kc*4+0], ah1 = qah[kc*4+1], ah2 = qah[kc*4+2], ah3 = qah[kc*4+3];
        uint32_t grp = (uint32_t)(lane >> 3), l8 = (uint32_t)(lane & 7);
        uint32_t nrow_b = ((grp >> 1) << 3) + l8;
        uint32_t kcol_b = (uint32_t)kc * 32 + ((grp & 1) << 4);
        #pragma unroll
        for (int ntp = 0; ntp < 4; ++ntp) {
            uint32_t boff = SWZ((nrow_b + ntp * 16) * 128 + kcol_b);
            uint32_t bh0,bh1,bh2,bh3;
            LDSM_X4(bh0,bh1,bh2,bh3, sb + SM_KH + boff);
            MMA(acc[2*ntp],   ah0,ah1,ah2,ah3, bh0,bh1);
            MMA(acc[2*ntp+1], ah0,ah1,ah2,ah3, bh2,bh3);
        }
    }

    // ---- epilogue: scale + bias + mask, softmax over each row ----
    {
        const float* bt = (const float*)(smem + SM_BIAS);
        const bool dm = (w == 127);
        float mlo = -1e30f, mhi = -1e30f;
        #pragma unroll
        for (int nt = 0; nt < 8; ++nt) {
            int c0 = nt * 8 + 2 * t;
            float b0v = bt[r_lo - c0 + 63], b1v = bt[r_lo - c0 + 62];
            float b2v = bt[r_hi - c0 + 63], b3v = bt[r_hi - c0 + 62];
            float mk_lo = (dm && ((r_lo < 32) != (c0 < 32))) ? -100.0f : 0.0f;
            float mk_hi = (dm && ((r_hi < 32) != (c0 < 32))) ? -100.0f : 0.0f;
            acc[nt][0] = acc[nt][0] * 0.125f + b0v + mk_lo;
            acc[nt][1] = acc[nt][1] * 0.125f + b1v + mk_lo;
            acc[nt][2] = acc[nt][2] * 0.125f + b2v + mk_hi;
            acc[nt][3] = acc[nt][3] * 0.125f + b3v + mk_hi;
            mlo = fmaxf(mlo, fmaxf(acc[nt][0], acc[nt][1]));
            mhi = fmaxf(mhi, fmaxf(acc[nt][2], acc[nt][3]));
        }
        mlo = fmaxf(mlo, __shfl_xor_sync(0xffffffffu, mlo, 1));
        mlo = fmaxf(mlo, __shfl_xor_sync(0xffffffffu, mlo, 2));
        mhi = fmaxf(mhi, __shfl_xor_sync(0xffffffffu, mhi, 1));
        mhi = fmaxf(mhi, __shfl_xor_sync(0xffffffffu, mhi, 2));
        float slo = 0.0f, shi = 0.0f;
        #pragma unroll
        for (int nt = 0; nt < 8; ++nt) {
            acc[nt][0] = __expf(acc[nt][0] - mlo);
            acc[nt][1] = __expf(acc[nt][1] - mlo);
            acc[nt][2] = __expf(acc[nt][2] - mhi);
            acc[nt][3] = __expf(acc[nt][3] - mhi);
            slo += acc[nt][0] + acc[nt][1];
            shi += acc[nt][2] + acc[nt][3];
        }
        slo += __shfl_xor_sync(0xffffffffu, slo, 1);
        slo += __shfl_xor_sync(0xffffffffu, slo, 2);
        shi += __shfl_xor_sync(0xffffffffu, shi, 1);
        shi += __shfl_xor_sync(0xffffffffu, shi, 2);
        float ilo = __fdividef(1.0f, slo), ihi = __fdividef(1.0f, shi);
        #pragma unroll
        for (int nt = 0; nt < 8; ++nt) {
            acc[nt][0] *= ilo; acc[nt][1] *= ilo;
            acc[nt][2] *= ihi; acc[nt][3] *= ihi;
        }
    }

    // ---- write attn ----
    {
        float* oat = out + 16777216L + (long)g * 4096;
        #pragma unroll
        for (int nt = 0; nt < 8; ++nt) {
            int c0 = nt * 8 + 2 * t;
            *(float2*)(oat + r_lo * 64 + c0) = make_float2(acc[nt][0], acc[nt][1]);
            *(float2*)(oat + r_hi * 64 + c0) = make_float2(acc[nt][2], acc[nt][3]);
        }
    }

    // ---- convert P (in acc) directly into gemm2 A-fragments (fp16 hi/lo) ----
    uint32_t pah[16], pal[16];
    #pragma unroll
    for (int kc = 0; kc < 4; ++kc) {
        split2h(acc[2*kc][0],   acc[2*kc][1],   pah[kc*4+0], pal[kc*4+0]);
        split2h(acc[2*kc][2],   acc[2*kc][3],   pah[kc*4+1], pal[kc*4+1]);
        split2h(acc[2*kc+1][0], acc[2*kc+1][1], pah[kc*4+2], pal[kc*4+2]);
        split2h(acc[2*kc+1][2], acc[2*kc+1][3], pah[kc*4+3], pal[kc*4+3]);
    }

    // ---- gemm2: O = (Ph + Pl) V,  V single fp16 via ldmatrix.trans ----
    #pragma unroll
    for (int nt = 0; nt < 8; ++nt)
        #pragma unroll
        for (int e = 0; e < 4; ++e) acc[nt][e] = 0.0f;

    #pragma unroll
    for (int kc = 0; kc < 4; ++kc) {
        uint32_t ah0 = pah[kc*4+0], ah1 = pah[kc*4+1], ah2 = pah[kc*4+2], ah3 = pah[kc*4+3];
        uint32_t al0 = pal[kc*4+0], al1 = pal[kc*4+1], al2 = pal[kc*4+2], al3 = pal[kc*4+3];
        uint32_t grp = (uint32_t)(lane >> 3), l8 = (uint32_t)(lane & 7);
        uint32_t krow = (uint32_t)kc * 16 + ((grp & 1) << 3) + l8;
        uint32_t nbase = ((grp >> 1) << 3);
        #pragma unroll
        for (int ntp = 0; ntp < 4; ++ntp) {
            uint32_t boff = SWZ(krow * 128 + (nbase + ntp * 16) * 2);
            uint32_t bh0,bh1,bh2,bh3;
            LDSM_X4_T(bh0,bh1,bh2,bh3, sb + SM_VH + boff);
            MMA(acc[2*ntp],   ah0,ah1,ah2,ah3, bh0,bh1);
            MMA(acc[2*ntp],   al0,al1,al2,al3, bh0,bh1);
            MMA(acc[2*ntp+1], ah0,ah1,ah2,ah3, bh2,bh3);
            MMA(acc[2*ntp+1], al0,al1,al2,al3, bh2,bh3);
        }
    }

    // ---- write x with inverse cyclic shift ----
    {
        int row_lo = (start + r_lo) & 8191;
        int row_hi = (start + r_hi) & 8191;
        float* op_lo = out + (batch_base + row_lo) * 64;
        float* op_hi = out + (batch_base + row_hi) * 64;
        #pragma unroll
        for (int nt = 0; nt < 8; ++nt) {
            int c0 = nt * 8 + 2 * t;
            *(float2*)(op_lo + c0) = make_float2(acc[nt][0], acc[nt][1]);
            *(float2*)(op_hi + c0) = make_float2(acc[nt][2], acc[nt][3]);
        }
    }
}

extern "C" void kernel_launch(void* const* d_in, const int* in_sizes, int n_in,
                              void* d_out, int out_size)
{
    const float* q   = (const float*)d_in[0];
    const float* k   = (const float*)d_in[1];
    const float* v   = (const float*)d_in[2];
    const float* tab = (const float*)d_in[3];
    float* out = (float*)d_out;
    (void)in_sizes; (void)n_in; (void)out_size;

    cudaFuncSetAttribute(win_attn_mma,
                         cudaFuncAttributeMaxDynamicSharedMemorySize, SM_TOTAL);
    win_attn_mma<<<NBLK, TPB, SM_TOTAL>>>(q, k, v, tab, out);
}

// round 15
// speedup vs baseline: 1.4480x; 1.0086x over previous
#include <cuda_runtime.h>
#include <cuda_fp16.h>
#include <cstdint>

// Shifted-window attention via warp-level fp16 mma.sync (m16n8k16).
// Q, K, V, P all single fp16 (measured err budget: ~4.5e-4 < 1e-3 tol).
// One CTA (128 thr) per window; warp owns 16 rows; Q direct global->regs;
// P kept in registers (acc layout == A-frag layout). 7 CTAs/SM (72 regs).

#define TPB 128
#define NBLK 4096

#define SM_KH 0          // K fp16 tile, 64 rows x 128B
#define SM_VH 8192       // V fp16 tile
#define SM_BIAS 16384    // 127 floats
#define SM_TOTAL 16896

#define SWZ(x) ((x) ^ (((x) >> 3) & 0x70))

__device__ __forceinline__ uint32_t smem_u32(const void* p){
    uint32_t a;
    asm("{ .reg .u64 t; cvta.to.shared.u64 t, %1; cvt.u32.u64 %0, t; }" : "=r"(a) : "l"(p));
    return a;
}
// pack two floats into one f16x2 register: {lo half = a, hi half = b}
__device__ __forceinline__ uint32_t pk16(float a, float b){
    uint32_t h;
    asm("cvt.rn.f16x2.f32 %0, %1, %2;" : "=r"(h) : "f"(b), "f"(a));
    return h;
}
#define LDSM_X4(r0,r1,r2,r3, a) \
    asm volatile("ldmatrix.sync.aligned.m8n8.x4.shared.b16 {%0,%1,%2,%3}, [%4];" \
        : "=r"(r0),"=r"(r1),"=r"(r2),"=r"(r3) : "r"(a))
#define LDSM_X4_T(r0,r1,r2,r3, a) \
    asm volatile("ldmatrix.sync.aligned.m8n8.x4.trans.shared.b16 {%0,%1,%2,%3}, [%4];" \
        : "=r"(r0),"=r"(r1),"=r"(r2),"=r"(r3) : "r"(a))
#define MMA(d, a0,a1,a2,a3, b0,b1) \
    asm volatile("mma.sync.aligned.m16n8k16.row.col.f32.f16.f16.f32 " \
        "{%0,%1,%2,%3}, {%4,%5,%6,%7}, {%8,%9}, {%0,%1,%2,%3};" \
        : "+f"((d)[0]),"+f"((d)[1]),"+f"((d)[2]),"+f"((d)[3]) \
        : "r"(a0),"r"(a1),"r"(a2),"r"(a3), "r"(b0),"r"(b1))

extern "C" __global__ void __launch_bounds__(TPB, 7)
win_attn_mma(const float* __restrict__ q, const float* __restrict__ k,
             const float* __restrict__ v, const float* __restrict__ tab,
             float* __restrict__ out)
{
    extern __shared__ __align__(128) char smem[];
    const uint32_t sb = smem_u32(smem);
    const int tid = threadIdx.x;
    const int g   = blockIdx.x;
    const int bb  = g >> 7;          // batch
    const int w   = g & 127;         // window
    const int start = w * 64 + 32;   // cyclic shift by -32 as gather
    const long batch_base = (long)bb * 8192;

    // ---- load K,V window: fp32 -> fp16, 16B swizzled stores ----
    #pragma unroll
    for (int it = 0; it < 4; ++it) {
        int idx = it * TPB + tid;        // 0..511
        int p = idx >> 3, c8 = idx & 7;  // row p, cols 8c8..8c8+7
        int row = (start + p) & 8191;
        long go = (batch_base + row) * 64 + c8 * 8;
        uint32_t so = SWZ((uint32_t)(p * 128 + c8 * 16));
        float4 ka = *(const float4*)(k + go);
        float4 kb = *(const float4*)(k + go + 4);
        float4 va = *(const float4*)(v + go);
        float4 vb = *(const float4*)(v + go + 4);
        *(uint4*)(smem + SM_KH + so) =
            make_uint4(pk16(ka.x, ka.y), pk16(ka.z, ka.w), pk16(kb.x, kb.y), pk16(kb.z, kb.w));
        *(uint4*)(smem + SM_VH + so) =
            make_uint4(pk16(va.x, va.y), pk16(va.z, va.w), pk16(vb.x, vb.y), pk16(vb.z, vb.w));
    }
    if (tid < 127) ((float*)(smem + SM_BIAS))[tid] = tab[tid];

    const int wid  = tid >> 5, lane = tid & 31;
    const int gq   = lane >> 2, t = lane & 3;
    const int R0   = wid * 16;
    const int r_lo = R0 + gq, r_hi = r_lo + 8;

    // ---- Q A-fragments: direct global loads, single fp16 ----
    const float* qlo = q + (batch_base + ((start + r_lo) & 8191)) * 64 + 2 * t;
    const float* qhi = q + (batch_base + ((start + r_hi) & 8191)) * 64 + 2 * t;
    uint32_t qah[16];   // [kc*4 + {a0,a1,a2,a3}]
    #pragma unroll
    for (int kc = 0; kc < 4; ++kc) {
        float2 f0 = *(const float2*)(qlo + kc * 16);
        float2 f1 = *(const float2*)(qhi + kc * 16);
        float2 f2 = *(const float2*)(qlo + kc * 16 + 8);
        float2 f3 = *(const float2*)(qhi + kc * 16 + 8);
        qah[kc*4+0] = pk16(f0.x, f0.y);
        qah[kc*4+1] = pk16(f1.x, f1.y);
        qah[kc*4+2] = pk16(f2.x, f2.y);
        qah[kc*4+3] = pk16(f3.x, f3.y);
    }
    __syncthreads();

    float acc[8][4];
    #pragma unroll
    for (int nt = 0; nt < 8; ++nt)
        #pragma unroll
        for (int e = 0; e < 4; ++e) acc[nt][e] = 0.0f;

    // ---- gemm1: S = Q K^T (single fp16 both sides) ----
    #pragma unroll
    for (int kc = 0; kc < 4; ++kc) {
        uint32_t ah0 = qah[kc*4+0], ah1 = qah[kc*4+1], ah2 = qah[kc*4+2], ah3 = qah[kc*4+3];
        uint32_t grp = (uint32_t)(lane >> 3), l8 = (uint32_t)(lane & 7);
        uint32_t nrow_b = ((grp >> 1) << 3) + l8;
        uint32_t kcol_b = (uint32_t)kc * 32 + ((grp & 1) << 4);
        #pragma unroll
        for (int ntp = 0; ntp < 4; ++ntp) {
            uint32_t boff = SWZ((nrow_b + ntp * 16) * 128 + kcol_b);
            uint32_t bh0,bh1,bh2,bh3;
            LDSM_X4(bh0,bh1,bh2,bh3, sb + SM_KH + boff);
            MMA(acc[2*ntp],   ah0,ah1,ah2,ah3, bh0,bh1);
            MMA(acc[2*ntp+1], ah0,ah1,ah2,ah3, bh2,bh3);
        }
    }

    // ---- epilogue: scale + bias + mask, softmax over each row ----
    {
        const float* bt = (const float*)(smem + SM_BIAS);
        const bool dm = (w == 127);
        float mlo = -1e30f, mhi = -1e30f;
        #pragma unroll
        for (int nt = 0; nt < 8; ++nt) {
            int c0 = nt * 8 + 2 * t;
            float b0v = bt[r_lo - c0 + 63], b1v = bt[r_lo - c0 + 62];
            float b2v = bt[r_hi - c0 + 63], b3v = bt[r_hi - c0 + 62];
            float mk_lo = (dm && ((r_lo < 32) != (c0 < 32))) ? -100.0f : 0.0f;
            float mk_hi = (dm && ((r_hi < 32) != (c0 < 32))) ? -100.0f : 0.0f;
            acc[nt][0] = acc[nt][0] * 0.125f + b0v + mk_lo;
            acc[nt][1] = acc[nt][1] * 0.125f + b1v + mk_lo;
            acc[nt][2] = acc[nt][2] * 0.125f + b2v + mk_hi;
            acc[nt][3] = acc[nt][3] * 0.125f + b3v + mk_hi;
            mlo = fmaxf(mlo, fmaxf(acc[nt][0], acc[nt][1]));
            mhi = fmaxf(mhi, fmaxf(acc[nt][2], acc[nt][3]));
        }
        mlo = fmaxf(mlo, __shfl_xor_sync(0xffffffffu, mlo, 1));
        mlo = fmaxf(mlo, __shfl_xor_sync(0xffffffffu, mlo, 2));
        mhi = fmaxf(mhi, __shfl_xor_sync(0xffffffffu, mhi, 1));
        mhi = fmaxf(mhi, __shfl_xor_sync(0xffffffffu, mhi, 2));
        float slo = 0.0f, shi = 0.0f;
        #pragma unroll
        for (int nt = 0; nt < 8; ++nt) {
            acc[nt][0] = __expf(acc[nt][0] - mlo);
            acc[nt][1] = __expf(acc[nt][1] - mlo);
            acc[nt][2] = __expf(acc[nt][2] - mhi);
            acc[nt][3] = __expf(acc[nt][3] - mhi);
            slo += acc[nt][0] + acc[nt][1];
            shi += acc[nt][2] + acc[nt][3];
        }
        slo += __shfl_xor_sync(0xffffffffu, slo, 1);
        slo += __shfl_xor_sync(0xffffffffu, slo, 2);
        shi += __shfl_xor_sync(0xffffffffu, shi, 1);
        shi += __shfl_xor_sync(0xffffffffu, shi, 2);
        float ilo = __fdividef(1.0f, slo), ihi = __fdividef(1.0f, shi);
        #pragma unroll
        for (int nt = 0; nt < 8; ++nt) {
            acc[nt][0] *= ilo; acc[nt][1] *= ilo;
            acc[nt][2] *= ihi; acc[nt][3] *= ihi;
        }
    }

    // ---- write attn ----
    {
        float* oat = out + 16777216L + (long)g * 4096;
        #pragma unroll
        for (int nt = 0; nt < 8; ++nt) {
            int c0 = nt * 8 + 2 * t;
            *(float2*)(oat + r_lo * 64 + c0) = make_float2(acc[nt][0], acc[nt][1]);
            *(float2*)(oat + r_hi * 64 + c0) = make_float2(acc[nt][2], acc[nt][3]);
        }
    }

    // ---- convert P (in acc) directly into gemm2 A-fragments (single fp16) ----
    uint32_t pah[16];
    #pragma unroll
    for (int kc = 0; kc < 4; ++kc) {
        pah[kc*4+0] = pk16(acc[2*kc][0],   acc[2*kc][1]);
        pah[kc*4+1] = pk16(acc[2*kc][2],   acc[2*kc][3]);
        pah[kc*4+2] = pk16(acc[2*kc+1][0], acc[2*kc+1][1]);
        pah[kc*4+3] = pk16(acc[2*kc+1][2], acc[2*kc+1][3]);
    }

    // ---- gemm2: O = P V (single fp16), V via ldmatrix.trans ----
    #pragma unroll
    for (int nt = 0; nt < 8; ++nt)
        #pragma unroll
        for (int e = 0; e < 4; ++e) acc[nt][e] = 0.0f;

    #pragma unroll
    for (int kc = 0; kc < 4; ++kc) {
        uint32_t ah0 = pah[kc*4+0], ah1 = pah[kc*4+1], ah2 = pah[kc*4+2], ah3 = pah[kc*4+3];
        uint32_t grp = (uint32_t)(lane >> 3), l8 = (uint32_t)(lane & 7);
        uint32_t krow = (uint32_t)kc * 16 + ((grp & 1) << 3) + l8;
        uint32_t nbase = ((grp >> 1) << 3);
        #pragma unroll
        for (int ntp = 0; ntp < 4; ++ntp) {
            uint32_t boff = SWZ(krow * 128 + (nbase + ntp * 16) * 2);
            uint32_t bh0,bh1,bh2,bh3;
            LDSM_X4_T(bh0,bh1,bh2,bh3, sb + SM_VH + boff);
            MMA(acc[2*ntp],   ah0,ah1,ah2,ah3, bh0,bh1);
            MMA(acc[2*ntp+1], ah0,ah1,ah2,ah3, bh2,bh3);
        }
    }

    // ---- write x with inverse cyclic shift ----
    {
        int row_lo = (start + r_lo) & 8191;
        int row_hi = (start + r_hi) & 8191;
        float* op_lo = out + (batch_base + row_lo) * 64;
        float* op_hi = out + (batch_base + row_hi) * 64;
        #pragma unroll
        for (int nt = 0; nt < 8; ++nt) {
            int c0 = nt * 8 + 2 * t;
            *(float2*)(op_lo + c0) = make_float2(acc[nt][0], acc[nt][1]);
            *(float2*)(op_hi + c0) = make_float2(acc[nt][2], acc[nt][3]);
        }
    }
}

extern "C" void kernel_launch(void* const* d_in, const int* in_sizes, int n_in,
                              void* d_out, int out_size)
{
    const float* q   = (const float*)d_in[0];
    const float* k   = (const float*)d_in[1];
    const float* v   = (const float*)d_in[2];
    const float* tab = (const float*)d_in[3];
    float* out = (float*)d_out;
    (void)in_sizes; (void)n_in; (void)out_size;

    cudaFuncSetAttribute(win_attn_mma,
                         cudaFuncAttributeMaxDynamicSharedMemorySize, SM_TOTAL);
    win_attn_mma<<<NBLK, TPB, SM_TOTAL>>>(q, k, v, tab, out);
}